// round 2
// baseline (speedup 1.0000x reference)
#include <cuda_runtime.h>
#include <cstdint>

// ---------------------------------------------------------------------------
// Problem: fused LayerNorm-LSTM cell.
//   v = [x|h] @ [W_ih|W_hh]^T + b_ih     (M=4096, N=4096, K=2048, fp32)
//   gates = LN_unbiased(v per gate, H=1024); f+=1
//   new_c = LN_unbiased(c*sig(f) + sig(i)*tanh(g))
//   new_h = tanh(new_c) * sig(o)
// Kernel 1: TF32 mma.sync GEMM -> g_V scratch.
// Kernel 2: per-batch-row LN + LSTM elementwise + LN + outputs.
// ---------------------------------------------------------------------------

#define BM 128
#define BN 128
#define BK 32
#define LDS_STRIDE 36                       // BK + 4 pad: conflict-free, rows stay 16B-aligned (144B)
#define STAGE_FLOATS ((BM + BN) * LDS_STRIDE)   // 9216 floats per stage
#define GEMM_SMEM_BYTES (2 * STAGE_FLOATS * (int)sizeof(float))  // 73728

__device__ float g_V[4096u * 4096u];        // 64 MB scratch for pre-LN gate activations

// ---- helpers ---------------------------------------------------------------

__device__ __forceinline__ void cp_async16(void* dst, const void* src) {
    uint32_t d = (uint32_t)__cvta_generic_to_shared(dst);
    asm volatile("cp.async.cg.shared.global [%0], [%1], 16;\n" :: "r"(d), "l"(src));
}

__device__ __forceinline__ uint32_t f2tf32(float f) {
    uint32_t u;
    asm("cvt.rna.tf32.f32 %0, %1;" : "=r"(u) : "f"(f));
    return u;
}

__device__ __forceinline__ void mma_tf32(float* d, const uint32_t* a, const uint32_t* b) {
    asm volatile(
        "mma.sync.aligned.m16n8k8.row.col.f32.tf32.tf32.f32 "
        "{%0,%1,%2,%3}, {%4,%5,%6,%7}, {%8,%9}, {%0,%1,%2,%3};\n"
        : "+f"(d[0]), "+f"(d[1]), "+f"(d[2]), "+f"(d[3])
        : "r"(a[0]), "r"(a[1]), "r"(a[2]), "r"(a[3]),
          "r"(b[0]), "r"(b[1]));
}

// ---- Kernel 1: GEMM --------------------------------------------------------
// v[m][n] = sum_k A[m,k] * W[n,k], A = [x | h], W = [W_ih | W_hh] (both K-major).

__global__ void gemm_gates(const float* __restrict__ x, const float* __restrict__ h,
                           const float* __restrict__ Wih, const float* __restrict__ Whh) {
    extern __shared__ float smem[];
    const int tid  = threadIdx.x;
    const int warp = tid >> 5;
    const int lane = tid & 31;
    const int wm = (warp & 3) * 32;          // warp row base within block tile
    const int wn = (warp >> 2) * 64;         // warp col base within block tile
    const int r  = lane >> 2;                // 0..7
    const int c4 = lane & 3;                 // 0..3
    const int bm0 = blockIdx.y * BM;
    const int bn0 = blockIdx.x * BN;

    float acc[2][8][4];
    #pragma unroll
    for (int i = 0; i < 2; i++)
        #pragma unroll
        for (int j = 0; j < 8; j++)
            #pragma unroll
            for (int k = 0; k < 4; k++) acc[i][j][k] = 0.f;

    const int row0 = tid >> 3;               // loader: row base (0..31), +32 per i
    const int colf = (tid & 7) * 4;          // loader: float4 column offset

    auto load_tile = [&](int kt, int stage) {
        const float* pa = (kt < 32 ? x   : h  ) + (size_t)bm0 * 1024 + (size_t)(kt & 31) * BK;
        const float* pb = (kt < 32 ? Wih : Whh) + (size_t)bn0 * 1024 + (size_t)(kt & 31) * BK;
        float* sa = smem + stage * STAGE_FLOATS;
        float* sb = sa + BM * LDS_STRIDE;
        #pragma unroll
        for (int i = 0; i < 4; i++) {
            int row = row0 + i * 32;
            cp_async16(sa + row * LDS_STRIDE + colf, pa + (size_t)row * 1024 + colf);
            cp_async16(sb + row * LDS_STRIDE + colf, pb + (size_t)row * 1024 + colf);
        }
        asm volatile("cp.async.commit_group;\n" ::: "memory");
    };

    const int NT = 2048 / BK;                // 64 K-tiles
    load_tile(0, 0);

    for (int kt = 0; kt < NT; kt++) {
        const int stage = kt & 1;
        if (kt + 1 < NT) {
            load_tile(kt + 1, stage ^ 1);
            asm volatile("cp.async.wait_group 1;\n" ::: "memory");
        } else {
            asm volatile("cp.async.wait_group 0;\n" ::: "memory");
        }
        __syncthreads();

        const float* sa = smem + stage * STAGE_FLOATS;
        const float* sb = sa + BM * LDS_STRIDE;

        #pragma unroll
        for (int ks = 0; ks < BK / 8; ks++) {
            uint32_t afr[2][4], bfr[8][2];
            #pragma unroll
            for (int mt = 0; mt < 2; mt++) {
                const float* p = sa + (wm + mt * 16 + r) * LDS_STRIDE + ks * 8 + c4;
                afr[mt][0] = f2tf32(p[0]);
                afr[mt][1] = f2tf32(p[8 * LDS_STRIDE]);
                afr[mt][2] = f2tf32(p[4]);
                afr[mt][3] = f2tf32(p[8 * LDS_STRIDE + 4]);
            }
            #pragma unroll
            for (int nt = 0; nt < 8; nt++) {
                const float* p = sb + (wn + nt * 8 + r) * LDS_STRIDE + ks * 8 + c4;
                bfr[nt][0] = f2tf32(p[0]);
                bfr[nt][1] = f2tf32(p[4]);
            }
            #pragma unroll
            for (int mt = 0; mt < 2; mt++)
                #pragma unroll
                for (int nt = 0; nt < 8; nt++)
                    mma_tf32(acc[mt][nt], afr[mt], bfr[nt]);
        }
        __syncthreads();
    }

    // epilogue: write v
    #pragma unroll
    for (int mt = 0; mt < 2; mt++) {
        #pragma unroll
        for (int nt = 0; nt < 8; nt++) {
            int m = bm0 + wm + mt * 16 + r;
            int n = bn0 + wn + nt * 8 + c4 * 2;
            *(float2*)&g_V[(size_t)m * 4096 + n]       = make_float2(acc[mt][nt][0], acc[mt][nt][1]);
            *(float2*)&g_V[(size_t)(m + 8) * 4096 + n] = make_float2(acc[mt][nt][2], acc[mt][nt][3]);
        }
    }
}

// ---- Kernel 2: LayerNorms + LSTM elementwise -------------------------------

__device__ __forceinline__ float sigm(float v) { return 1.f / (1.f + expf(-v)); }

__device__ __forceinline__ void block_reduce2(float& s, float& ss) {
    __shared__ float rs[8], rss[8];
    #pragma unroll
    for (int o = 16; o > 0; o >>= 1) {
        s  += __shfl_xor_sync(0xffffffffu, s,  o);
        ss += __shfl_xor_sync(0xffffffffu, ss, o);
    }
    const int w = threadIdx.x >> 5;
    if ((threadIdx.x & 31) == 0) { rs[w] = s; rss[w] = ss; }
    __syncthreads();
    float ts = 0.f, tss = 0.f;
    #pragma unroll
    for (int i = 0; i < 8; i++) { ts += rs[i]; tss += rss[i]; }
    __syncthreads();        // protect rs/rss before next reduction reuses them
    s = ts; ss = tss;
}

__global__ void ln_lstm(const float* __restrict__ c,
                        const float* __restrict__ b_ih,
                        const float* __restrict__ gamma_ifgo, const float* __restrict__ beta_ifgo,
                        const float* __restrict__ gamma_c,    const float* __restrict__ beta_c,
                        float* __restrict__ out) {
    const int b   = blockIdx.x;              // batch row, 0..4095
    const int tid = threadIdx.x;             // 0..255, each owns 4 consecutive H-elems per gate

    const float4* vb   = (const float4*)(g_V + (size_t)b * 4096);
    const float4* bih4 = (const float4*)b_ih;

    float4 gate[4];
    #pragma unroll
    for (int g = 0; g < 4; g++) {
        float4 w  = vb[g * 256 + tid];
        float4 bb = bih4[g * 256 + tid];
        w.x += bb.x; w.y += bb.y; w.z += bb.z; w.w += bb.w;

        float s  = w.x + w.y + w.z + w.w;
        float ss = w.x * w.x + w.y * w.y + w.z * w.z + w.w * w.w;
        block_reduce2(s, ss);

        float mean = s * (1.f / 1024.f);
        float var  = fmaxf(ss - s * mean, 0.f) * (1.f / 1023.f);   // unbiased
        float inv  = 1.f / (sqrtf(var) + 1e-6f);

        float4 ga = ((const float4*)gamma_ifgo)[g * 256 + tid];
        float4 be = ((const float4*)beta_ifgo)[g * 256 + tid];
        gate[g].x = ga.x * (w.x - mean) * inv + be.x;
        gate[g].y = ga.y * (w.y - mean) * inv + be.y;
        gate[g].z = ga.z * (w.z - mean) * inv + be.z;
        gate[g].w = ga.w * (w.w - mean) * inv + be.w;
    }

    // LSTM elementwise: i=gate[0], f=gate[1]+1, g=gate[2], o=gate[3]
    float4 ci = ((const float4*)(c + (size_t)b * 1024))[tid];
    float4 cc;
    cc.x = ci.x * sigm(gate[1].x + 1.f) + sigm(gate[0].x) * tanhf(gate[2].x);
    cc.y = ci.y * sigm(gate[1].y + 1.f) + sigm(gate[0].y) * tanhf(gate[2].y);
    cc.z = ci.z * sigm(gate[1].z + 1.f) + sigm(gate[0].z) * tanhf(gate[2].z);
    cc.w = ci.w * sigm(gate[1].w + 1.f) + sigm(gate[0].w) * tanhf(gate[2].w);

    // LN over new_c
    float s  = cc.x + cc.y + cc.z + cc.w;
    float ss = cc.x * cc.x + cc.y * cc.y + cc.z * cc.z + cc.w * cc.w;
    block_reduce2(s, ss);
    float mean = s * (1.f / 1024.f);
    float var  = fmaxf(ss - s * mean, 0.f) * (1.f / 1023.f);
    float inv  = 1.f / (sqrtf(var) + 1e-6f);

    float4 gc = ((const float4*)gamma_c)[tid];
    float4 bc = ((const float4*)beta_c)[tid];
    float4 nc, nh;
    nc.x = gc.x * (cc.x - mean) * inv + bc.x;  nh.x = tanhf(nc.x) * sigm(gate[3].x);
    nc.y = gc.y * (cc.y - mean) * inv + bc.y;  nh.y = tanhf(nc.y) * sigm(gate[3].y);
    nc.z = gc.z * (cc.z - mean) * inv + bc.z;  nh.z = tanhf(nc.z) * sigm(gate[3].z);
    nc.w = gc.w * (cc.w - mean) * inv + bc.w;  nh.w = tanhf(nc.w) * sigm(gate[3].w);

    // out = [new_h (B*H) | new_c (B*H)]
    ((float4*)out)[(size_t)b * 256 + tid]                        = nh;
    ((float4*)out)[(size_t)4096 * 256 + (size_t)b * 256 + tid]   = nc;
}

// ---- launch ----------------------------------------------------------------

extern "C" void kernel_launch(void* const* d_in, const int* in_sizes, int n_in,
                              void* d_out, int out_size) {
    const float* x     = (const float*)d_in[0];
    const float* h     = (const float*)d_in[1];
    const float* c     = (const float*)d_in[2];
    const float* Wih   = (const float*)d_in[3];
    const float* bih   = (const float*)d_in[4];
    const float* Whh   = (const float*)d_in[5];
    const float* gifgo = (const float*)d_in[6];
    const float* bifgo = (const float*)d_in[7];
    const float* gc    = (const float*)d_in[8];
    const float* bc    = (const float*)d_in[9];
    float* out = (float*)d_out;

    cudaFuncSetAttribute(gemm_gates, cudaFuncAttributeMaxDynamicSharedMemorySize,
                         GEMM_SMEM_BYTES);

    dim3 grid(4096 / BN, 4096 / BM);     // 32 x 32 tiles
    gemm_gates<<<grid, 256, GEMM_SMEM_BYTES>>>(x, h, Wih, Whh);
    ln_lstm<<<4096, 256>>>(c, bih, gifgo, bifgo, gc, bc, out);
}

// round 4
// speedup vs baseline: 1.0412x; 1.0412x over previous
#include <cuda_runtime.h>
#include <cstdint>

// ---------------------------------------------------------------------------
// Fused LayerNorm-LSTM cell, sm_100 legacy-tensor-path build.
//   Pre-pass: RNA-round inputs to TF32, pack A=[x|h], W=[Wih|Whh] (K=2048 rows)
//   GEMM:     v = A @ W^T via mma.sync.m16n8k8.tf32, 128x256 tiles -> g_V
//   Epilogue: per-row 4x LN + LSTM + LN -> out
// ---------------------------------------------------------------------------

#define BM 128
#define BN 256
#define BK 32
#define NS 4
#define NT 64                                  // 2048 / BK
#define A_BYTES (BM * 128)                     // 16384
#define STAGE_BYTES ((BM + BN) * 128)          // 49152
#define SMEM_SZ (NS * STAGE_BYTES + 1024)

__device__ float g_V[4096u * 4096u];           // 64 MB: pre-LN gate activations
__device__ float g_A[4096u * 2048u];           // 32 MB: rounded [x|h]
__device__ float g_W[4096u * 2048u];           // 32 MB: rounded [Wih|Whh]

// ---- helpers ---------------------------------------------------------------

__device__ __forceinline__ uint32_t s2u(const void* p) {
    return (uint32_t)__cvta_generic_to_shared(p);
}
__device__ __forceinline__ void cp_async16(uint32_t dst, const void* src) {
    asm volatile("cp.async.cg.shared.global [%0], [%1], 16;\n" :: "r"(dst), "l"(src));
}
__device__ __forceinline__ void cp_commit() {
    asm volatile("cp.async.commit_group;\n" ::: "memory");
}
template <int N> __device__ __forceinline__ void cp_wait() {
    asm volatile("cp.async.wait_group %0;\n" :: "n"(N) : "memory");
}
__device__ __forceinline__ uint32_t f2tf32(float f) {
    uint32_t u;
    asm("cvt.rna.tf32.f32 %0, %1;" : "=r"(u) : "f"(f));
    return u;
}
__device__ __forceinline__ void lds128(uint32_t* v, uint32_t a) {
    asm volatile("ld.shared.v4.b32 {%0,%1,%2,%3}, [%4];"
                 : "=r"(v[0]), "=r"(v[1]), "=r"(v[2]), "=r"(v[3]) : "r"(a));
}
__device__ __forceinline__ void mma_tf32(float* d, uint32_t a0, uint32_t a1,
                                         uint32_t a2, uint32_t a3,
                                         uint32_t b0, uint32_t b1) {
    asm volatile(
        "mma.sync.aligned.m16n8k8.row.col.f32.tf32.tf32.f32 "
        "{%0,%1,%2,%3}, {%4,%5,%6,%7}, {%8,%9}, {%0,%1,%2,%3};\n"
        : "+f"(d[0]), "+f"(d[1]), "+f"(d[2]), "+f"(d[3])
        : "r"(a0), "r"(a1), "r"(a2), "r"(a3), "r"(b0), "r"(b1));
}

// ---- Kernel 0: RNA-round + pack --------------------------------------------
// i in [0, 4M) float4: first 2M -> g_A rows of 2048 ([x row | h row]),
// second 2M -> g_W rows of 2048 ([Wih row | Whh row]).

__global__ __launch_bounds__(256)
void preround(const float* __restrict__ x, const float* __restrict__ h,
              const float* __restrict__ Wih, const float* __restrict__ Whh) {
    const uint32_t i = blockIdx.x * 256u + threadIdx.x;        // 0 .. 4M-1
    const uint32_t half = i >> 21;
    const uint32_t j = i & 0x1FFFFFu;
    const uint32_t row = j >> 9;                               // 512 float4 per row
    const uint32_t c = j & 511u;

    const float4* src;
    float* dst;
    if (half == 0) {
        src = (c < 256u) ? ((const float4*)x + (size_t)row * 256 + c)
                         : ((const float4*)h + (size_t)row * 256 + (c - 256u));
        dst = g_A + (size_t)row * 2048 + c * 4;
    } else {
        src = (c < 256u) ? ((const float4*)Wih + (size_t)row * 256 + c)
                         : ((const float4*)Whh + (size_t)row * 256 + (c - 256u));
        dst = g_W + (size_t)row * 2048 + c * 4;
    }
    float4 v = *src;
    uint4 o;
    o.x = f2tf32(v.x); o.y = f2tf32(v.y); o.z = f2tf32(v.z); o.w = f2tf32(v.w);
    *(uint4*)dst = o;
}

// ---- Kernel 1: GEMM --------------------------------------------------------
// Smem layout per stage: A rows (128B each, 8 x 16B granules, granule g of row
// rw stored at g ^ ((rw&1)*4)), then B rows likewise. The XOR swizzle makes
// every ld.shared.v4 phase bank-conflict-free; logical-k permutation is shared
// by A and B so the GEMM sum is unchanged.

__global__ __launch_bounds__(256, 1)
void gemm_tc(const float* __restrict__ gA, const float* __restrict__ gW) {
    extern __shared__ float dsm[];
    const uint32_t dyn0 = s2u(dsm);
    const uint32_t base = (dyn0 + 1023u) & ~1023u;

    const int tid  = threadIdx.x;
    const int warp = tid >> 5;
    const int lane = tid & 31;
    const int wm = (warp & 1) * 64;            // 2 x 4 warp grid, 64x64 warp tile
    const int wn = (warp >> 1) * 64;
    const int r  = lane >> 2;                  // 0..7
    const int c4 = lane & 3;                   // 0..3
    const uint32_t xo = (uint32_t)(r & 1) << 2;
    const int bm0 = blockIdx.y * BM;
    const int bn0 = blockIdx.x * BN;

    float acc[4][8][4];
    #pragma unroll
    for (int i = 0; i < 4; i++)
        #pragma unroll
        for (int j = 0; j < 8; j++)
            #pragma unroll
            for (int k = 0; k < 4; k++) acc[i][j][k] = 0.f;

    // loader geometry
    const int lrow = tid >> 3;                 // 0..31
    const int lch  = tid & 7;                  // 16B chunk in row

    auto issue_loads = [&](int j) {
        const uint32_t sb = base + (uint32_t)(j & (NS - 1)) * STAGE_BYTES;
        const int kc = j * BK;
        #pragma unroll
        for (int i = 0; i < 4; i++) {          // A: 128 rows
            int row = lrow + i * 32;
            uint32_t dst = sb + (uint32_t)row * 128u + ((uint32_t)(lch ^ ((row & 1) << 2)) << 4);
            cp_async16(dst, gA + (size_t)(bm0 + row) * 2048 + kc + lch * 4);
        }
        #pragma unroll
        for (int i = 0; i < 8; i++) {          // B: 256 rows
            int row = lrow + i * 32;
            uint32_t dst = sb + A_BYTES + (uint32_t)row * 128u + ((uint32_t)(lch ^ ((row & 1) << 2)) << 4);
            cp_async16(dst, gW + (size_t)(bn0 + row) * 2048 + kc + lch * 4);
        }
        cp_commit();
    };

    issue_loads(0); issue_loads(1); issue_loads(2);

    for (int kt = 0; kt < NT; kt++) {
        const int rem = (NT - 1) - kt;
        if (rem >= 2)      cp_wait<2>();
        else if (rem == 1) cp_wait<1>();
        else               cp_wait<0>();
        __syncthreads();                        // stage kt ready; stage kt-1 reads done

        if (kt + NS - 1 < NT) issue_loads(kt + NS - 1);

        const uint32_t sA = base + (uint32_t)(kt & (NS - 1)) * STAGE_BYTES;
        const uint32_t sB = sA + A_BYTES;

        #pragma unroll
        for (int q = 0; q < 2; q++) {
            const uint32_t gq = ((uint32_t)((q << 2) + c4) ^ xo) << 4;
            uint32_t a[4][2][4], b[8][4];
            #pragma unroll
            for (int mt = 0; mt < 4; mt++) {
                uint32_t ad = sA + (uint32_t)(wm + mt * 16 + r) * 128u + gq;
                lds128(a[mt][0], ad);
                lds128(a[mt][1], ad + 8 * 128);
            }
            #pragma unroll
            for (int nt = 0; nt < 8; nt++)
                lds128(b[nt], sB + (uint32_t)(wn + nt * 8 + r) * 128u + gq);

            #pragma unroll
            for (int m2 = 0; m2 < 2; m2++)
                #pragma unroll
                for (int mt = 0; mt < 4; mt++)
                    #pragma unroll
                    for (int nt = 0; nt < 8; nt++)
                        mma_tf32(acc[mt][nt],
                                 a[mt][0][2 * m2], a[mt][1][2 * m2],
                                 a[mt][0][2 * m2 + 1], a[mt][1][2 * m2 + 1],
                                 b[nt][2 * m2], b[nt][2 * m2 + 1]);
        }
    }

    // epilogue: direct STG of fragments
    #pragma unroll
    for (int mt = 0; mt < 4; mt++) {
        #pragma unroll
        for (int nt = 0; nt < 8; nt++) {
            int m = bm0 + wm + mt * 16 + r;
            int n = bn0 + wn + nt * 8 + c4 * 2;
            *(float2*)&g_V[(size_t)m * 4096 + n]       = make_float2(acc[mt][nt][0], acc[mt][nt][1]);
            *(float2*)&g_V[(size_t)(m + 8) * 4096 + n] = make_float2(acc[mt][nt][2], acc[mt][nt][3]);
        }
    }
}

// ---- Kernel 2: LayerNorms + LSTM elementwise (2 barriers) ------------------

__device__ __forceinline__ float sigm(float v) { return 1.f / (1.f + expf(-v)); }

__global__ __launch_bounds__(256)
void ln_lstm(const float* __restrict__ c,
             const float* __restrict__ b_ih,
             const float* __restrict__ gamma_ifgo, const float* __restrict__ beta_ifgo,
             const float* __restrict__ gamma_c,    const float* __restrict__ beta_c,
             float* __restrict__ out) {
    __shared__ float red[8][8];
    __shared__ float red2[8][2];

    const int b   = blockIdx.x;
    const int tid = threadIdx.x;
    const int w   = tid >> 5;

    const float4* vb   = (const float4*)(g_V + (size_t)b * 4096);
    const float4* bih4 = (const float4*)b_ih;

    float4 wv[4];
    float  s[4], ss[4];
    #pragma unroll
    for (int g = 0; g < 4; g++) {
        float4 t  = vb[g * 256 + tid];
        float4 bb = bih4[g * 256 + tid];
        t.x += bb.x; t.y += bb.y; t.z += bb.z; t.w += bb.w;
        wv[g] = t;
        s[g]  = t.x + t.y + t.z + t.w;
        ss[g] = t.x * t.x + t.y * t.y + t.z * t.z + t.w * t.w;
    }
    #pragma unroll
    for (int o = 16; o > 0; o >>= 1) {
        #pragma unroll
        for (int g = 0; g < 4; g++) {
            s[g]  += __shfl_xor_sync(0xffffffffu, s[g],  o);
            ss[g] += __shfl_xor_sync(0xffffffffu, ss[g], o);
        }
    }
    if ((tid & 31) == 0) {
        #pragma unroll
        for (int g = 0; g < 4; g++) { red[w][g * 2] = s[g]; red[w][g * 2 + 1] = ss[g]; }
    }
    __syncthreads();

    float4 gate[4];
    #pragma unroll
    for (int g = 0; g < 4; g++) {
        float S = 0.f, SS = 0.f;
        #pragma unroll
        for (int i = 0; i < 8; i++) { S += red[i][g * 2]; SS += red[i][g * 2 + 1]; }
        float mean = S * (1.f / 1024.f);
        float var  = fmaxf(SS - S * mean, 0.f) * (1.f / 1023.f);
        float inv  = 1.f / (sqrtf(var) + 1e-6f);
        float4 ga = ((const float4*)gamma_ifgo)[g * 256 + tid];
        float4 be = ((const float4*)beta_ifgo)[g * 256 + tid];
        gate[g].x = ga.x * (wv[g].x - mean) * inv + be.x;
        gate[g].y = ga.y * (wv[g].y - mean) * inv + be.y;
        gate[g].z = ga.z * (wv[g].z - mean) * inv + be.z;
        gate[g].w = ga.w * (wv[g].w - mean) * inv + be.w;
    }

    float4 ci = ((const float4*)(c + (size_t)b * 1024))[tid];
    float4 cc;
    cc.x = ci.x * sigm(gate[1].x + 1.f) + sigm(gate[0].x) * tanhf(gate[2].x);
    cc.y = ci.y * sigm(gate[1].y + 1.f) + sigm(gate[0].y) * tanhf(gate[2].y);
    cc.z = ci.z * sigm(gate[1].z + 1.f) + sigm(gate[0].z) * tanhf(gate[2].z);
    cc.w = ci.w * sigm(gate[1].w + 1.f) + sigm(gate[0].w) * tanhf(gate[2].w);

    float s2  = cc.x + cc.y + cc.z + cc.w;
    float ss2 = cc.x * cc.x + cc.y * cc.y + cc.z * cc.z + cc.w * cc.w;
    #pragma unroll
    for (int o = 16; o > 0; o >>= 1) {
        s2  += __shfl_xor_sync(0xffffffffu, s2,  o);
        ss2 += __shfl_xor_sync(0xffffffffu, ss2, o);
    }
    if ((tid & 31) == 0) { red2[w][0] = s2; red2[w][1] = ss2; }
    __syncthreads();
    float S = 0.f, SS = 0.f;
    #pragma unroll
    for (int i = 0; i < 8; i++) { S += red2[i][0]; SS += red2[i][1]; }
    float mean = S * (1.f / 1024.f);
    float var  = fmaxf(SS - S * mean, 0.f) * (1.f / 1023.f);
    float inv  = 1.f / (sqrtf(var) + 1e-6f);

    float4 gc = ((const float4*)gamma_c)[tid];
    float4 bc = ((const float4*)beta_c)[tid];
    float4 nc, nh;
    nc.x = gc.x * (cc.x - mean) * inv + bc.x;  nh.x = tanhf(nc.x) * sigm(gate[3].x);
    nc.y = gc.y * (cc.y - mean) * inv + bc.y;  nh.y = tanhf(nc.y) * sigm(gate[3].y);
    nc.z = gc.z * (cc.z - mean) * inv + bc.z;  nh.z = tanhf(nc.z) * sigm(gate[3].z);
    nc.w = gc.w * (cc.w - mean) * inv + bc.w;  nh.w = tanhf(nc.w) * sigm(gate[3].w);

    ((float4*)out)[(size_t)b * 256 + tid]                      = nh;
    ((float4*)out)[(size_t)4096 * 256 + (size_t)b * 256 + tid] = nc;
}

// ---- launch ----------------------------------------------------------------

extern "C" void kernel_launch(void* const* d_in, const int* in_sizes, int n_in,
                              void* d_out, int out_size) {
    const float* x     = (const float*)d_in[0];
    const float* h     = (const float*)d_in[1];
    const float* c     = (const float*)d_in[2];
    const float* Wih   = (const float*)d_in[3];
    const float* bih   = (const float*)d_in[4];
    const float* Whh   = (const float*)d_in[5];
    const float* gifgo = (const float*)d_in[6];
    const float* bifgo = (const float*)d_in[7];
    const float* gc    = (const float*)d_in[8];
    const float* bc    = (const float*)d_in[9];
    float* out = (float*)d_out;

    float* gA; cudaGetSymbolAddress((void**)&gA, g_A);
    float* gW; cudaGetSymbolAddress((void**)&gW, g_W);

    cudaFuncSetAttribute(gemm_tc, cudaFuncAttributeMaxDynamicSharedMemorySize, SMEM_SZ);

    preround<<<16384, 256>>>(x, h, Wih, Whh);
    dim3 grid(4096 / BN, 4096 / BM);            // 16 x 32
    gemm_tc<<<grid, 256, SMEM_SZ>>>(gA, gW);
    ln_lstm<<<4096, 256>>>(c, bih, gifgo, bifgo, gc, bc, out);
}

// round 7
// speedup vs baseline: 1.1818x; 1.1350x over previous
#include <cuda_runtime.h>
#include <cstdint>

// ---------------------------------------------------------------------------
// Fused LayerNorm-LSTM cell, sm_100. GEMM via legacy int8 IMMA (m16n8k32)
// using an exact-ish 15-bit fixed-point split: q = hi*128 + lo (hi,lo in s8).
//   v ~= (G1*2^14 + G2*2^7) / (SA*SW),  G1 = hiA.hiB, G2 = hiA.loB + loA.hiB
// (lo.lo dropped: zero-mean, ~2^-12.5 relative).
// ---------------------------------------------------------------------------

#define BM 128
#define BN 128
#define BK 32                       // k-bytes per stage row
#define NS 8
#define NT 64                       // 2048 / 32
#define PLANE_BYTES (128 * 32)      // 4096 per plane per stage
#define STAGE_BYTES (4 * PLANE_BYTES)   // Ahi, Alo, Bhi, Blo = 16384
#define SMEM_SZ (NS * STAGE_BYTES + 1024)

#define SA 2709.3333f               // 16256 / 6.0
#define SW 86698.6667f              // 16256 / (6.0/32)
#define INV_S (1.0f / (2709.3333f * 86698.6667f))

__device__ float   g_V[4096u * 4096u];     // 64 MB pre-LN gate activations
__device__ uint8_t g_Ahi[4096u * 2048u];   // quantized [x|h], k-permuted
__device__ uint8_t g_Alo[4096u * 2048u];
__device__ uint8_t g_Whi[4096u * 2048u];   // quantized [Wih|Whh], k-permuted
__device__ uint8_t g_Wlo[4096u * 2048u];

// ---- helpers ---------------------------------------------------------------

__device__ __forceinline__ uint32_t s2u(const void* p) {
    return (uint32_t)__cvta_generic_to_shared(p);
}
__device__ __forceinline__ void cp_async16(uint32_t dst, const void* src) {
    asm volatile("cp.async.cg.shared.global [%0], [%1], 16;\n" :: "r"(dst), "l"(src));
}
__device__ __forceinline__ void cp_commit() {
    asm volatile("cp.async.commit_group;\n" ::: "memory");
}
template <int N> __device__ __forceinline__ void cp_wait() {
    asm volatile("cp.async.wait_group %0;\n" :: "n"(N) : "memory");
}
__device__ __forceinline__ void lds64(uint32_t& x, uint32_t& y, uint32_t a) {
    asm volatile("ld.shared.v2.b32 {%0,%1}, [%2];" : "=r"(x), "=r"(y) : "r"(a));
}
__device__ __forceinline__ void mma_s8(int* d, const uint32_t* a, const uint32_t* b) {
    asm volatile(
        "mma.sync.aligned.m16n8k32.row.col.s32.s8.s8.s32 "
        "{%0,%1,%2,%3}, {%4,%5,%6,%7}, {%8,%9}, {%0,%1,%2,%3};\n"
        : "+r"(d[0]), "+r"(d[1]), "+r"(d[2]), "+r"(d[3])
        : "r"(a[0]), "r"(a[1]), "r"(a[2]), "r"(a[3]), "r"(b[0]), "r"(b[1]));
}

// ---- Kernel 0: quantize + split + k-permute --------------------------------
// One thread = one 32-k chunk of one row. Stored byte order within a chunk:
// pos = ((k&15)>>2)*8 + (k>>4)*4 + (k&3)  -> fragment regs become contiguous.

__global__ __launch_bounds__(256)
void quantize(const float* __restrict__ x, const float* __restrict__ h,
              const float* __restrict__ Wih, const float* __restrict__ Whh) {
    const uint32_t idx = blockIdx.x * 256u + threadIdx.x;   // 0 .. 524287
    const uint32_t tensor = idx >> 18;                      // 0=A, 1=W
    const uint32_t j = idx & 0x3FFFFu;
    const uint32_t row = j >> 6;
    const uint32_t chunk = j & 63u;

    const float* src;
    uint8_t *dhi, *dlo;
    float S;
    if (tensor == 0) {
        src = (chunk < 32u) ? x + (size_t)row * 1024 + chunk * 32
                            : h + (size_t)row * 1024 + (chunk - 32u) * 32;
        dhi = g_Ahi; dlo = g_Alo; S = SA;
    } else {
        src = (chunk < 32u) ? Wih + (size_t)row * 1024 + chunk * 32
                            : Whh + (size_t)row * 1024 + (chunk - 32u) * 32;
        dhi = g_Whi; dlo = g_Wlo; S = SW;
    }

    float f[32];
    #pragma unroll
    for (int i = 0; i < 8; i++) {
        float4 v = ((const float4*)src)[i];
        f[i * 4 + 0] = v.x; f[i * 4 + 1] = v.y; f[i * 4 + 2] = v.z; f[i * 4 + 3] = v.w;
    }

    union { uint8_t b[32]; uint4 u[2]; } hi, lo;
    #pragma unroll
    for (int i = 0; i < 32; i++) {
        float q = rintf(f[i] * S);
        q = fmaxf(-16256.f, fminf(16256.f, q));
        float hq = rintf(q * (1.f / 128.f));
        float lq = q - 128.f * hq;
        int pos = ((i & 15) >> 2) * 8 + (i >> 4) * 4 + (i & 3);
        hi.b[pos] = (uint8_t)(int8_t)(int)hq;
        lo.b[pos] = (uint8_t)(int8_t)(int)lq;
    }
    const size_t off = (size_t)row * 2048 + chunk * 32;
    ((uint4*)(dhi + off))[0] = hi.u[0];
    ((uint4*)(dhi + off))[1] = hi.u[1];
    ((uint4*)(dlo + off))[0] = lo.u[0];
    ((uint4*)(dlo + off))[1] = lo.u[1];
}

// ---- Kernel 1: int8 split GEMM ---------------------------------------------

__global__ __launch_bounds__(256, 1)
void gemm_i8(const uint8_t* __restrict__ gAhi, const uint8_t* __restrict__ gAlo,
             const uint8_t* __restrict__ gWhi, const uint8_t* __restrict__ gWlo) {
    extern __shared__ float dsm[];
    const uint32_t dyn0 = s2u(dsm);
    const uint32_t base = (dyn0 + 1023u) & ~1023u;

    const int tid  = threadIdx.x;
    const int warp = tid >> 5;
    const int lane = tid & 31;
    const int g    = lane >> 2;               // 0..7
    const int c4   = lane & 3;                // 0..3
    const int wm = (warp & 1) * 64;           // 2 x 4 warp grid, 64x32 warp tile
    const int wn = (warp >> 1) * 32;
    const int bm0 = blockIdx.y * BM;
    const int bn0 = blockIdx.x * BN;

    int acc1[4][4][4], acc2[4][4][4];
    #pragma unroll
    for (int i = 0; i < 4; i++)
        #pragma unroll
        for (int j = 0; j < 4; j++)
            #pragma unroll
            for (int k = 0; k < 4; k++) { acc1[i][j][k] = 0; acc2[i][j][k] = 0; }

    // loader: each thread moves one 16B chunk per plane per stage
    const int lrow  = tid >> 1;               // 0..127
    const int lhalf = (tid & 1) * 16;

    auto issue_loads = [&](int kt) {
        const uint32_t sb = base + (uint32_t)(kt & (NS - 1)) * STAGE_BYTES;
        const uint32_t so = (uint32_t)lrow * 32u + (uint32_t)lhalf;
        const size_t  goA = (size_t)(bm0 + lrow) * 2048 + kt * 32 + lhalf;
        const size_t  goB = (size_t)(bn0 + lrow) * 2048 + kt * 32 + lhalf;
        cp_async16(sb + so,                   gAhi + goA);
        cp_async16(sb + PLANE_BYTES + so,     gAlo + goA);
        cp_async16(sb + 2 * PLANE_BYTES + so, gWhi + goB);
        cp_async16(sb + 3 * PLANE_BYTES + so, gWlo + goB);
        cp_commit();
    };

    #pragma unroll
    for (int s = 0; s < NS - 1; s++) issue_loads(s);

    for (int kt = 0; kt < NT; kt++) {
        const int rem = (NT - 1) - kt;
        if      (rem >= 6) cp_wait<6>();
        else if (rem == 5) cp_wait<5>();
        else if (rem == 4) cp_wait<4>();
        else if (rem == 3) cp_wait<3>();
        else if (rem == 2) cp_wait<2>();
        else if (rem == 1) cp_wait<1>();
        else               cp_wait<0>();
        __syncthreads();

        if (kt + NS - 1 < NT) issue_loads(kt + NS - 1);

        const uint32_t sb  = base + (uint32_t)(kt & (NS - 1)) * STAGE_BYTES;
        const uint32_t aof = (uint32_t)c4 * 8u;

        uint32_t Ah[4][4], Al[4][4], Bh[4][2], Bl[4][2];
        #pragma unroll
        for (int mt = 0; mt < 4; mt++) {
            uint32_t ad = sb + (uint32_t)(wm + mt * 16 + g) * 32u + aof;
            lds64(Ah[mt][0], Ah[mt][2], ad);
            lds64(Ah[mt][1], Ah[mt][3], ad + 8 * 32);
            lds64(Al[mt][0], Al[mt][2], ad + PLANE_BYTES);
            lds64(Al[mt][1], Al[mt][3], ad + PLANE_BYTES + 8 * 32);
        }
        #pragma unroll
        for (int nt = 0; nt < 4; nt++) {
            uint32_t bd = sb + 2 * PLANE_BYTES + (uint32_t)(wn + nt * 8 + g) * 32u + aof;
            lds64(Bh[nt][0], Bh[nt][1], bd);
            lds64(Bl[nt][0], Bl[nt][1], bd + PLANE_BYTES);
        }

        #pragma unroll
        for (int mt = 0; mt < 4; mt++)
            #pragma unroll
            for (int nt = 0; nt < 4; nt++)
                mma_s8(acc1[mt][nt], Ah[mt], Bh[nt]);
        #pragma unroll
        for (int mt = 0; mt < 4; mt++)
            #pragma unroll
            for (int nt = 0; nt < 4; nt++)
                mma_s8(acc2[mt][nt], Ah[mt], Bl[nt]);
        #pragma unroll
        for (int mt = 0; mt < 4; mt++)
            #pragma unroll
            for (int nt = 0; nt < 4; nt++)
                mma_s8(acc2[mt][nt], Al[mt], Bh[nt]);
    }

    // epilogue: combine and store float v
    #pragma unroll
    for (int mt = 0; mt < 4; mt++) {
        #pragma unroll
        for (int nt = 0; nt < 4; nt++) {
            int m = bm0 + wm + mt * 16 + g;
            int n = bn0 + wn + nt * 8 + c4 * 2;
            float v0 = ((float)acc1[mt][nt][0] * 16384.f + (float)acc2[mt][nt][0] * 128.f) * INV_S;
            float v1 = ((float)acc1[mt][nt][1] * 16384.f + (float)acc2[mt][nt][1] * 128.f) * INV_S;
            float v2 = ((float)acc1[mt][nt][2] * 16384.f + (float)acc2[mt][nt][2] * 128.f) * INV_S;
            float v3 = ((float)acc1[mt][nt][3] * 16384.f + (float)acc2[mt][nt][3] * 128.f) * INV_S;
            *(float2*)&g_V[(size_t)m * 4096 + n]       = make_float2(v0, v1);
            *(float2*)&g_V[(size_t)(m + 8) * 4096 + n] = make_float2(v2, v3);
        }
    }
}

// ---- Kernel 2: LayerNorms + LSTM elementwise -------------------------------

__device__ __forceinline__ float sigm(float v) { return 1.f / (1.f + expf(-v)); }

__global__ __launch_bounds__(256)
void ln_lstm(const float* __restrict__ c,
             const float* __restrict__ b_ih,
             const float* __restrict__ gamma_ifgo, const float* __restrict__ beta_ifgo,
             const float* __restrict__ gamma_c,    const float* __restrict__ beta_c,
             float* __restrict__ out) {
    __shared__ float red[8][8];
    __shared__ float red2[8][2];

    const int b   = blockIdx.x;
    const int tid = threadIdx.x;
    const int w   = tid >> 5;

    const float4* vb   = (const float4*)(g_V + (size_t)b * 4096);
    const float4* bih4 = (const float4*)b_ih;

    float4 wv[4];
    float  s[4], ss[4];
    #pragma unroll
    for (int g = 0; g < 4; g++) {
        float4 t  = vb[g * 256 + tid];
        float4 bb = bih4[g * 256 + tid];
        t.x += bb.x; t.y += bb.y; t.z += bb.z; t.w += bb.w;
        wv[g] = t;
        s[g]  = t.x + t.y + t.z + t.w;
        ss[g] = t.x * t.x + t.y * t.y + t.z * t.z + t.w * t.w;
    }
    #pragma unroll
    for (int o = 16; o > 0; o >>= 1) {
        #pragma unroll
        for (int g = 0; g < 4; g++) {
            s[g]  += __shfl_xor_sync(0xffffffffu, s[g],  o);
            ss[g] += __shfl_xor_sync(0xffffffffu, ss[g], o);
        }
    }
    if ((tid & 31) == 0) {
        #pragma unroll
        for (int g = 0; g < 4; g++) { red[w][g * 2] = s[g]; red[w][g * 2 + 1] = ss[g]; }
    }
    __syncthreads();

    float4 gate[4];
    #pragma unroll
    for (int g = 0; g < 4; g++) {
        float S = 0.f, SS = 0.f;
        #pragma unroll
        for (int i = 0; i < 8; i++) { S += red[i][g * 2]; SS += red[i][g * 2 + 1]; }
        float mean = S * (1.f / 1024.f);
        float var  = fmaxf(SS - S * mean, 0.f) * (1.f / 1023.f);
        float inv  = 1.f / (sqrtf(var) + 1e-6f);
        float4 ga = ((const float4*)gamma_ifgo)[g * 256 + tid];
        float4 be = ((const float4*)beta_ifgo)[g * 256 + tid];
        gate[g].x = ga.x * (wv[g].x - mean) * inv + be.x;
        gate[g].y = ga.y * (wv[g].y - mean) * inv + be.y;
        gate[g].z = ga.z * (wv[g].z - mean) * inv + be.z;
        gate[g].w = ga.w * (wv[g].w - mean) * inv + be.w;
    }

    float4 ci = ((const float4*)(c + (size_t)b * 1024))[tid];
    float4 cc;
    cc.x = ci.x * sigm(gate[1].x + 1.f) + sigm(gate[0].x) * tanhf(gate[2].x);
    cc.y = ci.y * sigm(gate[1].y + 1.f) + sigm(gate[0].y) * tanhf(gate[2].y);
    cc.z = ci.z * sigm(gate[1].z + 1.f) + sigm(gate[0].z) * tanhf(gate[2].z);
    cc.w = ci.w * sigm(gate[1].w + 1.f) + sigm(gate[0].w) * tanhf(gate[2].w);

    float s2  = cc.x + cc.y + cc.z + cc.w;
    float ss2 = cc.x * cc.x + cc.y * cc.y + cc.z * cc.z + cc.w * cc.w;
    #pragma unroll
    for (int o = 16; o > 0; o >>= 1) {
        s2  += __shfl_xor_sync(0xffffffffu, s2,  o);
        ss2 += __shfl_xor_sync(0xffffffffu, ss2, o);
    }
    if ((tid & 31) == 0) { red2[w][0] = s2; red2[w][1] = ss2; }
    __syncthreads();
    float S = 0.f, SS = 0.f;
    #pragma unroll
    for (int i = 0; i < 8; i++) { S += red2[i][0]; SS += red2[i][1]; }
    float mean = S * (1.f / 1024.f);
    float var  = fmaxf(SS - S * mean, 0.f) * (1.f / 1023.f);
    float inv  = 1.f / (sqrtf(var) + 1e-6f);

    float4 gc = ((const float4*)gamma_c)[tid];
    float4 bc = ((const float4*)beta_c)[tid];
    float4 nc, nh;
    nc.x = gc.x * (cc.x - mean) * inv + bc.x;  nh.x = tanhf(nc.x) * sigm(gate[3].x);
    nc.y = gc.y * (cc.y - mean) * inv + bc.y;  nh.y = tanhf(nc.y) * sigm(gate[3].y);
    nc.z = gc.z * (cc.z - mean) * inv + bc.z;  nh.z = tanhf(nc.z) * sigm(gate[3].z);
    nc.w = gc.w * (cc.w - mean) * inv + bc.w;  nh.w = tanhf(nc.w) * sigm(gate[3].w);

    ((float4*)out)[(size_t)b * 256 + tid]                      = nh;
    ((float4*)out)[(size_t)4096 * 256 + (size_t)b * 256 + tid] = nc;
}

// ---- launch ----------------------------------------------------------------

extern "C" void kernel_launch(void* const* d_in, const int* in_sizes, int n_in,
                              void* d_out, int out_size) {
    const float* x     = (const float*)d_in[0];
    const float* h     = (const float*)d_in[1];
    const float* c     = (const float*)d_in[2];
    const float* Wih   = (const float*)d_in[3];
    const float* bih   = (const float*)d_in[4];
    const float* Whh   = (const float*)d_in[5];
    const float* gifgo = (const float*)d_in[6];
    const float* bifgo = (const float*)d_in[7];
    const float* gc    = (const float*)d_in[8];
    const float* bc    = (const float*)d_in[9];
    float* out = (float*)d_out;

    uint8_t *gAhi, *gAlo, *gWhi, *gWlo;
    cudaGetSymbolAddress((void**)&gAhi, g_Ahi);
    cudaGetSymbolAddress((void**)&gAlo, g_Alo);
    cudaGetSymbolAddress((void**)&gWhi, g_Whi);
    cudaGetSymbolAddress((void**)&gWlo, g_Wlo);

    cudaFuncSetAttribute(gemm_i8, cudaFuncAttributeMaxDynamicSharedMemorySize, SMEM_SZ);

    quantize<<<2048, 256>>>(x, h, Wih, Whh);
    dim3 grid(4096 / BN, 4096 / BM);            // 32 x 32
    gemm_i8<<<grid, 256, SMEM_SZ>>>(gAhi, gAlo, gWhi, gWlo);
    ln_lstm<<<4096, 256>>>(c, bih, gifgo, bifgo, gc, bc, out);
}

// round 8
// speedup vs baseline: 1.2435x; 1.0522x over previous
#include <cuda_runtime.h>
#include <cuda_fp16.h>
#include <cstdint>

// ---------------------------------------------------------------------------
// Fused LayerNorm-LSTM cell, sm_100 legacy tensor path.
//   Kernel 0: convert x,h -> g_A (fp16), Wih,Whh -> g_W (fp16), k-permuted so
//             m16n8k16 fragments are single lds.128 ops.
//   Kernel 1: v = A @ W^T via mma.sync.m16n8k16.f16 (16.8M instrs) -> g_V f32
//   Kernel 2: 4x LN + LSTM elementwise + LN -> out
// ---------------------------------------------------------------------------

#define BM 128
#define BN 256
#define BKH 64                          // k halfs per stage (128 B per row)
#define NS 4
#define NT 32                           // 2048 / 64
#define A_BYTES (BM * 128)              // 16384
#define STAGE_BYTES ((BM + BN) * 128)   // 49152
#define SMEM_SZ (NS * STAGE_BYTES + 1024)

__device__ float  g_V[4096u * 4096u];   // 64 MB pre-LN gate activations
__device__ __half g_A[4096u * 2048u];   // 16 MB fp16 [x|h], k-permuted
__device__ __half g_W[4096u * 2048u];   // 16 MB fp16 [Wih|Whh], k-permuted

// ---- helpers ---------------------------------------------------------------

__device__ __forceinline__ uint32_t s2u(const void* p) {
    return (uint32_t)__cvta_generic_to_shared(p);
}
__device__ __forceinline__ void cp_async16(uint32_t dst, const void* src) {
    asm volatile("cp.async.cg.shared.global [%0], [%1], 16;\n" :: "r"(dst), "l"(src));
}
__device__ __forceinline__ void cp_commit() {
    asm volatile("cp.async.commit_group;\n" ::: "memory");
}
template <int N> __device__ __forceinline__ void cp_wait() {
    asm volatile("cp.async.wait_group %0;\n" :: "n"(N) : "memory");
}
__device__ __forceinline__ void lds128(uint32_t* v, uint32_t a) {
    asm volatile("ld.shared.v4.b32 {%0,%1,%2,%3}, [%4];"
                 : "=r"(v[0]), "=r"(v[1]), "=r"(v[2]), "=r"(v[3]) : "r"(a));
}
__device__ __forceinline__ void mma_f16(float* d, uint32_t a0, uint32_t a1,
                                        uint32_t a2, uint32_t a3,
                                        uint32_t b0, uint32_t b1) {
    asm volatile(
        "mma.sync.aligned.m16n8k16.row.col.f32.f16.f16.f32 "
        "{%0,%1,%2,%3}, {%4,%5,%6,%7}, {%8,%9}, {%0,%1,%2,%3};\n"
        : "+f"(d[0]), "+f"(d[1]), "+f"(d[2]), "+f"(d[3])
        : "r"(a0), "r"(a1), "r"(a2), "r"(a3), "r"(b0), "r"(b1));
}

// ---- Kernel 0: fp16 convert + k-permute ------------------------------------
// One thread = one 32-half k-block of one row. Permuted position within the
// block: pos = ((k>>1)&3)*8 + ((k>>4)&1)*4 + ((k>>3)&1)*2 + (k&1).
// Thread t's 16B at offset t*16 then holds exactly {a0_s0, a2_s0, a0_s1, a2_s1}
// (k-pairs {2t,2t+1} and {2t+8,2t+9} for both 16-k steps) = canonical fragment.

__global__ __launch_bounds__(256)
void tohalf(const float* __restrict__ x, const float* __restrict__ h,
            const float* __restrict__ Wih, const float* __restrict__ Whh) {
    const uint32_t idx = blockIdx.x * 256u + threadIdx.x;   // 0 .. 524287
    const uint32_t tensor = idx >> 18;                      // 0=A, 1=W
    const uint32_t j = idx & 0x3FFFFu;
    const uint32_t row = j >> 6;
    const uint32_t chunk = j & 63u;                         // 32-half blocks per row

    const float* src;
    __half* dst;
    if (tensor == 0) {
        src = (chunk < 32u) ? x + (size_t)row * 1024 + chunk * 32
                            : h + (size_t)row * 1024 + (chunk - 32u) * 32;
        dst = g_A + (size_t)row * 2048 + chunk * 32;
    } else {
        src = (chunk < 32u) ? Wih + (size_t)row * 1024 + chunk * 32
                            : Whh + (size_t)row * 1024 + (chunk - 32u) * 32;
        dst = g_W + (size_t)row * 2048 + chunk * 32;
    }

    float f[32];
    #pragma unroll
    for (int i = 0; i < 8; i++) {
        float4 v = ((const float4*)src)[i];
        f[i * 4 + 0] = v.x; f[i * 4 + 1] = v.y; f[i * 4 + 2] = v.z; f[i * 4 + 3] = v.w;
    }

    union { __half hh[32]; uint4 u[4]; } o;
    #pragma unroll
    for (int k = 0; k < 32; k++) {
        int pos = ((k >> 1) & 3) * 8 + ((k >> 4) & 1) * 4 + ((k >> 3) & 1) * 2 + (k & 1);
        o.hh[pos] = __float2half_rn(f[k]);
    }
    #pragma unroll
    for (int i = 0; i < 4; i++) ((uint4*)dst)[i] = o.u[i];
}

// ---- Kernel 1: fp16 GEMM ---------------------------------------------------
// Smem: per stage, A rows then B rows, 128 B each (one 64-half k-chunk).
// 64B-granule XOR-by-row-parity swizzle -> all lds.128 phases conflict-free.

__global__ __launch_bounds__(256, 1)
void gemm_f16(const __half* __restrict__ gA, const __half* __restrict__ gW) {
    extern __shared__ float dsm[];
    const uint32_t dyn0 = s2u(dsm);
    const uint32_t base = (dyn0 + 1023u) & ~1023u;

    const int tid  = threadIdx.x;
    const int warp = tid >> 5;
    const int lane = tid & 31;
    const int g    = lane >> 2;               // 0..7
    const int t4   = lane & 3;                // 0..3
    const int wm = (warp & 1) * 64;           // 2 x 4 warp grid, 64x64 warp tile
    const int wn = (warp >> 1) * 64;
    const int bm0 = blockIdx.y * BM;
    const int bn0 = blockIdx.x * BN;
    const uint32_t gpar = (uint32_t)(g & 1);

    float acc[4][8][4];
    #pragma unroll
    for (int i = 0; i < 4; i++)
        #pragma unroll
        for (int j = 0; j < 8; j++)
            #pragma unroll
            for (int k = 0; k < 4; k++) acc[i][j][k] = 0.f;

    // loader geometry
    const int alrow = tid >> 1;               // 0..127 (A rows)
    const int ac0   = (tid & 1) * 4;          // A: 4 chunks per thread

    auto issue_loads = [&](int kt) {
        const uint32_t sb = base + (uint32_t)(kt & (NS - 1)) * STAGE_BYTES;
        // A: 128 rows x 8 chunks, 2 threads/row
        {
            const uint32_t sw = (uint32_t)(alrow & 1) << 2;
            const __half* srow = gA + (size_t)(bm0 + alrow) * 2048 + kt * BKH;
            #pragma unroll
            for (int j = 0; j < 4; j++) {
                int c = ac0 + j;
                cp_async16(sb + (uint32_t)alrow * 128u + ((uint32_t)c ^ sw) * 16u,
                           srow + c * 8);
            }
        }
        // B: 256 rows x 8 chunks, 1 thread/row
        {
            const uint32_t sw = (uint32_t)(tid & 1) << 2;
            const __half* srow = gW + (size_t)(bn0 + tid) * 2048 + kt * BKH;
            #pragma unroll
            for (int c = 0; c < 8; c++) {
                cp_async16(sb + A_BYTES + (uint32_t)tid * 128u + ((uint32_t)c ^ sw) * 16u,
                           srow + c * 8);
            }
        }
        cp_commit();
    };

    issue_loads(0); issue_loads(1); issue_loads(2);

    for (int kt = 0; kt < NT; kt++) {
        const int rem = (NT - 1) - kt;
        if (rem >= 2)      cp_wait<2>();
        else if (rem == 1) cp_wait<1>();
        else               cp_wait<0>();
        __syncthreads();

        if (kt + NS - 1 < NT) issue_loads(kt + NS - 1);

        const uint32_t sA = base + (uint32_t)(kt & (NS - 1)) * STAGE_BYTES;
        const uint32_t sB = sA + A_BYTES;

        #pragma unroll
        for (int i = 0; i < 2; i++) {                     // 32-half sub-blocks
            const uint32_t ie  = ((uint32_t)i ^ gpar) * 64u;
            const uint32_t tof = (uint32_t)t4 * 16u;

            uint32_t A0[4][4], A8[4][4], B[8][4];
            #pragma unroll
            for (int mt = 0; mt < 4; mt++) {
                uint32_t ad = sA + (uint32_t)(wm + mt * 16 + g) * 128u + ie + tof;
                lds128(A0[mt], ad);
                lds128(A8[mt], ad + 8 * 128);
            }
            #pragma unroll
            for (int nt = 0; nt < 8; nt++)
                lds128(B[nt], sB + (uint32_t)(wn + nt * 8 + g) * 128u + ie + tof);

            #pragma unroll
            for (int s = 0; s < 2; s++)                   // two k16 steps
                #pragma unroll
                for (int mt = 0; mt < 4; mt++)
                    #pragma unroll
                    for (int nt = 0; nt < 8; nt++)
                        mma_f16(acc[mt][nt],
                                A0[mt][2 * s], A8[mt][2 * s],
                                A0[mt][2 * s + 1], A8[mt][2 * s + 1],
                                B[nt][2 * s], B[nt][2 * s + 1]);
        }
    }

    // epilogue: direct STG of fragments
    #pragma unroll
    for (int mt = 0; mt < 4; mt++) {
        #pragma unroll
        for (int nt = 0; nt < 8; nt++) {
            int m = bm0 + wm + mt * 16 + g;
            int n = bn0 + wn + nt * 8 + t4 * 2;
            *(float2*)&g_V[(size_t)m * 4096 + n]       = make_float2(acc[mt][nt][0], acc[mt][nt][1]);
            *(float2*)&g_V[(size_t)(m + 8) * 4096 + n] = make_float2(acc[mt][nt][2], acc[mt][nt][3]);
        }
    }
}

// ---- Kernel 2: LayerNorms + LSTM elementwise -------------------------------

__device__ __forceinline__ float sigm(float v) { return 1.f / (1.f + expf(-v)); }

__global__ __launch_bounds__(256)
void ln_lstm(const float* __restrict__ c,
             const float* __restrict__ b_ih,
             const float* __restrict__ gamma_ifgo, const float* __restrict__ beta_ifgo,
             const float* __restrict__ gamma_c,    const float* __restrict__ beta_c,
             float* __restrict__ out) {
    __shared__ float red[8][8];
    __shared__ float red2[8][2];

    const int b   = blockIdx.x;
    const int tid = threadIdx.x;
    const int w   = tid >> 5;

    const float4* vb   = (const float4*)(g_V + (size_t)b * 4096);
    const float4* bih4 = (const float4*)b_ih;

    float4 wv[4];
    float  s[4], ss[4];
    #pragma unroll
    for (int g = 0; g < 4; g++) {
        float4 t  = vb[g * 256 + tid];
        float4 bb = bih4[g * 256 + tid];
        t.x += bb.x; t.y += bb.y; t.z += bb.z; t.w += bb.w;
        wv[g] = t;
        s[g]  = t.x + t.y + t.z + t.w;
        ss[g] = t.x * t.x + t.y * t.y + t.z * t.z + t.w * t.w;
    }
    #pragma unroll
    for (int o = 16; o > 0; o >>= 1) {
        #pragma unroll
        for (int g = 0; g < 4; g++) {
            s[g]  += __shfl_xor_sync(0xffffffffu, s[g],  o);
            ss[g] += __shfl_xor_sync(0xffffffffu, ss[g], o);
        }
    }
    if ((tid & 31) == 0) {
        #pragma unroll
        for (int g = 0; g < 4; g++) { red[w][g * 2] = s[g]; red[w][g * 2 + 1] = ss[g]; }
    }
    __syncthreads();

    float4 gate[4];
    #pragma unroll
    for (int g = 0; g < 4; g++) {
        float S = 0.f, SS = 0.f;
        #pragma unroll
        for (int i = 0; i < 8; i++) { S += red[i][g * 2]; SS += red[i][g * 2 + 1]; }
        float mean = S * (1.f / 1024.f);
        float var  = fmaxf(SS - S * mean, 0.f) * (1.f / 1023.f);
        float inv  = 1.f / (sqrtf(var) + 1e-6f);
        float4 ga = ((const float4*)gamma_ifgo)[g * 256 + tid];
        float4 be = ((const float4*)beta_ifgo)[g * 256 + tid];
        gate[g].x = ga.x * (wv[g].x - mean) * inv + be.x;
        gate[g].y = ga.y * (wv[g].y - mean) * inv + be.y;
        gate[g].z = ga.z * (wv[g].z - mean) * inv + be.z;
        gate[g].w = ga.w * (wv[g].w - mean) * inv + be.w;
    }

    float4 ci = ((const float4*)(c + (size_t)b * 1024))[tid];
    float4 cc;
    cc.x = ci.x * sigm(gate[1].x + 1.f) + sigm(gate[0].x) * tanhf(gate[2].x);
    cc.y = ci.y * sigm(gate[1].y + 1.f) + sigm(gate[0].y) * tanhf(gate[2].y);
    cc.z = ci.z * sigm(gate[1].z + 1.f) + sigm(gate[0].z) * tanhf(gate[2].z);
    cc.w = ci.w * sigm(gate[1].w + 1.f) + sigm(gate[0].w) * tanhf(gate[2].w);

    float s2  = cc.x + cc.y + cc.z + cc.w;
    float ss2 = cc.x * cc.x + cc.y * cc.y + cc.z * cc.z + cc.w * cc.w;
    #pragma unroll
    for (int o = 16; o > 0; o >>= 1) {
        s2  += __shfl_xor_sync(0xffffffffu, s2,  o);
        ss2 += __shfl_xor_sync(0xffffffffu, ss2, o);
    }
    if ((tid & 31) == 0) { red2[w][0] = s2; red2[w][1] = ss2; }
    __syncthreads();
    float S = 0.f, SS = 0.f;
    #pragma unroll
    for (int i = 0; i < 8; i++) { S += red2[i][0]; SS += red2[i][1]; }
    float mean = S * (1.f / 1024.f);
    float var  = fmaxf(SS - S * mean, 0.f) * (1.f / 1023.f);
    float inv  = 1.f / (sqrtf(var) + 1e-6f);

    float4 gc = ((const float4*)gamma_c)[tid];
    float4 bc = ((const float4*)beta_c)[tid];
    float4 nc, nh;
    nc.x = gc.x * (cc.x - mean) * inv + bc.x;  nh.x = tanhf(nc.x) * sigm(gate[3].x);
    nc.y = gc.y * (cc.y - mean) * inv + bc.y;  nh.y = tanhf(nc.y) * sigm(gate[3].y);
    nc.z = gc.z * (cc.z - mean) * inv + bc.z;  nh.z = tanhf(nc.z) * sigm(gate[3].z);
    nc.w = gc.w * (cc.w - mean) * inv + bc.w;  nh.w = tanhf(nc.w) * sigm(gate[3].w);

    ((float4*)out)[(size_t)b * 256 + tid]                      = nh;
    ((float4*)out)[(size_t)4096 * 256 + (size_t)b * 256 + tid] = nc;
}

// ---- launch ----------------------------------------------------------------

extern "C" void kernel_launch(void* const* d_in, const int* in_sizes, int n_in,
                              void* d_out, int out_size) {
    const float* x     = (const float*)d_in[0];
    const float* h     = (const float*)d_in[1];
    const float* c     = (const float*)d_in[2];
    const float* Wih   = (const float*)d_in[3];
    const float* bih   = (const float*)d_in[4];
    const float* Whh   = (const float*)d_in[5];
    const float* gifgo = (const float*)d_in[6];
    const float* bifgo = (const float*)d_in[7];
    const float* gc    = (const float*)d_in[8];
    const float* bc    = (const float*)d_in[9];
    float* out = (float*)d_out;

    __half *gA, *gW;
    cudaGetSymbolAddress((void**)&gA, g_A);
    cudaGetSymbolAddress((void**)&gW, g_W);

    cudaFuncSetAttribute(gemm_f16, cudaFuncAttributeMaxDynamicSharedMemorySize, SMEM_SZ);

    tohalf<<<2048, 256>>>(x, h, Wih, Whh);
    dim3 grid(4096 / BN, 4096 / BM);            // 16 x 32
    gemm_f16<<<grid, 256, SMEM_SZ>>>(gA, gW);
    ln_lstm<<<4096, 256>>>(c, bih, gifgo, bifgo, gc, bc, out);
}

// round 10
// speedup vs baseline: 1.5998x; 1.2866x over previous
#include <cuda_runtime.h>
#include <cuda_fp16.h>
#include <cstdint>

// ---------------------------------------------------------------------------
// Fused LayerNorm-LSTM cell, sm_100 legacy tensor path.
//   Kernel 0: convert x,h -> g_A (fp16), Wih,Whh -> g_W (fp16), k-permuted so
//             m16n8k16 fragments are single lds.128 ops.
//   Kernel 1: v = A @ W^T via mma.sync.m16n8k16.f16 -> g_V f32
//             128x128 tiles, 64x32 warp tiles, NS=3, 2 CTAs/SM.
//   Kernel 2: 4x LN + LSTM elementwise + LN -> out
// ---------------------------------------------------------------------------

#define BM 128
#define BN 128
#define BKH 64                          // k halfs per stage (128 B per row)
#define NS 3
#define NT 32                           // 2048 / 64
#define A_BYTES (BM * 128)              // 16384
#define STAGE_BYTES ((BM + BN) * 128)   // 32768
#define SMEM_SZ (NS * STAGE_BYTES + 1024)   // 99328

__device__ float  g_V[4096u * 4096u];   // 64 MB pre-LN gate activations
__device__ __half g_A[4096u * 2048u];   // 16 MB fp16 [x|h], k-permuted
__device__ __half g_W[4096u * 2048u];   // 16 MB fp16 [Wih|Whh], k-permuted

// ---- helpers ---------------------------------------------------------------

__device__ __forceinline__ uint32_t s2u(const void* p) {
    return (uint32_t)__cvta_generic_to_shared(p);
}
__device__ __forceinline__ void cp_async16(uint32_t dst, const void* src) {
    asm volatile("cp.async.cg.shared.global [%0], [%1], 16;\n" :: "r"(dst), "l"(src));
}
__device__ __forceinline__ void cp_commit() {
    asm volatile("cp.async.commit_group;\n" ::: "memory");
}
template <int N> __device__ __forceinline__ void cp_wait() {
    asm volatile("cp.async.wait_group %0;\n" :: "n"(N) : "memory");
}
__device__ __forceinline__ void lds128(uint32_t* v, uint32_t a) {
    asm volatile("ld.shared.v4.b32 {%0,%1,%2,%3}, [%4];"
                 : "=r"(v[0]), "=r"(v[1]), "=r"(v[2]), "=r"(v[3]) : "r"(a));
}
__device__ __forceinline__ void mma_f16(float* d, uint32_t a0, uint32_t a1,
                                        uint32_t a2, uint32_t a3,
                                        uint32_t b0, uint32_t b1) {
    asm volatile(
        "mma.sync.aligned.m16n8k16.row.col.f32.f16.f16.f32 "
        "{%0,%1,%2,%3}, {%4,%5,%6,%7}, {%8,%9}, {%0,%1,%2,%3};\n"
        : "+f"(d[0]), "+f"(d[1]), "+f"(d[2]), "+f"(d[3])
        : "r"(a0), "r"(a1), "r"(a2), "r"(a3), "r"(b0), "r"(b1));
}

// ---- Kernel 0: fp16 convert + k-permute ------------------------------------
// pos = ((k>>1)&3)*8 + ((k>>4)&1)*4 + ((k>>3)&1)*2 + (k&1): thread t's 16B at
// offset t*16 holds k-pairs {2t,2t+1},{2t+8,2t+9} for both k16 steps.

__global__ __launch_bounds__(256)
void tohalf(const float* __restrict__ x, const float* __restrict__ h,
            const float* __restrict__ Wih, const float* __restrict__ Whh) {
    const uint32_t idx = blockIdx.x * 256u + threadIdx.x;   // 0 .. 524287
    const uint32_t tensor = idx >> 18;                      // 0=A, 1=W
    const uint32_t j = idx & 0x3FFFFu;
    const uint32_t row = j >> 6;
    const uint32_t chunk = j & 63u;

    const float* src;
    __half* dst;
    if (tensor == 0) {
        src = (chunk < 32u) ? x + (size_t)row * 1024 + chunk * 32
                            : h + (size_t)row * 1024 + (chunk - 32u) * 32;
        dst = g_A + (size_t)row * 2048 + chunk * 32;
    } else {
        src = (chunk < 32u) ? Wih + (size_t)row * 1024 + chunk * 32
                            : Whh + (size_t)row * 1024 + (chunk - 32u) * 32;
        dst = g_W + (size_t)row * 2048 + chunk * 32;
    }

    float f[32];
    #pragma unroll
    for (int i = 0; i < 8; i++) {
        float4 v = ((const float4*)src)[i];
        f[i * 4 + 0] = v.x; f[i * 4 + 1] = v.y; f[i * 4 + 2] = v.z; f[i * 4 + 3] = v.w;
    }

    union { __half hh[32]; uint4 u[4]; } o;
    #pragma unroll
    for (int k = 0; k < 32; k++) {
        int pos = ((k >> 1) & 3) * 8 + ((k >> 4) & 1) * 4 + ((k >> 3) & 1) * 2 + (k & 1);
        o.hh[pos] = __float2half_rn(f[k]);
    }
    #pragma unroll
    for (int i = 0; i < 4; i++) ((uint4*)dst)[i] = o.u[i];
}

// ---- Kernel 1: fp16 GEMM, 2 CTAs/SM ----------------------------------------
// Per stage: A rows then B rows, 128 B each. 64B-granule parity swizzle keeps
// every 8-lane lds.128 phase on 32 distinct banks.

__global__ __launch_bounds__(256, 2)
void gemm_f16(const __half* __restrict__ gA, const __half* __restrict__ gW) {
    extern __shared__ float dsm[];
    const uint32_t dyn0 = s2u(dsm);
    const uint32_t base = (dyn0 + 1023u) & ~1023u;

    const int tid  = threadIdx.x;
    const int warp = tid >> 5;
    const int lane = tid & 31;
    const int g    = lane >> 2;               // 0..7
    const int t4   = lane & 3;                // 0..3
    const int wm = (warp & 1) * 64;           // 2 x 4 warp grid, 64x32 warp tile
    const int wn = (warp >> 1) * 32;
    const int bm0 = blockIdx.y * BM;
    const int bn0 = blockIdx.x * BN;
    const uint32_t gpar = (uint32_t)(g & 1);

    float acc[4][4][4];
    #pragma unroll
    for (int i = 0; i < 4; i++)
        #pragma unroll
        for (int j = 0; j < 4; j++)
            #pragma unroll
            for (int k = 0; k < 4; k++) acc[i][j][k] = 0.f;

    // loader: 2 threads/row, 4 chunks each, for both A (128 rows) and B (128)
    const int lrow = tid >> 1;
    const int lc0  = (tid & 1) * 4;
    const uint32_t lsw = (uint32_t)(lrow & 1) << 2;

    auto issue_loads = [&](int kt) {
        const uint32_t sb = base + (uint32_t)(kt % NS) * STAGE_BYTES;
        const __half* arow = gA + (size_t)(bm0 + lrow) * 2048 + kt * BKH;
        const __half* brow = gW + (size_t)(bn0 + lrow) * 2048 + kt * BKH;
        #pragma unroll
        for (int j = 0; j < 4; j++) {
            int c = lc0 + j;
            uint32_t coff = ((uint32_t)c ^ lsw) * 16u;
            cp_async16(sb + (uint32_t)lrow * 128u + coff,           arow + c * 8);
            cp_async16(sb + A_BYTES + (uint32_t)lrow * 128u + coff, brow + c * 8);
        }
        cp_commit();
    };

    issue_loads(0); issue_loads(1);

    for (int kt = 0; kt < NT; kt++) {
        if (kt < NT - 1) cp_wait<1>();
        else             cp_wait<0>();
        __syncthreads();

        if (kt + NS - 1 < NT) issue_loads(kt + NS - 1);

        const uint32_t sA = base + (uint32_t)(kt % NS) * STAGE_BYTES;
        const uint32_t sB = sA + A_BYTES;
        const uint32_t tof = (uint32_t)t4 * 16u;

        #pragma unroll
        for (int i = 0; i < 2; i++) {                     // 32-half sub-blocks
            const uint32_t ie = ((uint32_t)i ^ gpar) * 64u;

            uint32_t B[4][4];
            #pragma unroll
            for (int nt = 0; nt < 4; nt++)
                lds128(B[nt], sB + (uint32_t)(wn + nt * 8 + g) * 128u + ie + tof);

            #pragma unroll
            for (int mh = 0; mh < 2; mh++) {              // mt pairs: low A reg pressure
                uint32_t A0[2][4], A8[2][4];
                #pragma unroll
                for (int m2 = 0; m2 < 2; m2++) {
                    uint32_t ad = sA + (uint32_t)(wm + (mh * 2 + m2) * 16 + g) * 128u + ie + tof;
                    lds128(A0[m2], ad);
                    lds128(A8[m2], ad + 8 * 128);
                }
                #pragma unroll
                for (int s = 0; s < 2; s++)               // two k16 steps
                    #pragma unroll
                    for (int m2 = 0; m2 < 2; m2++)
                        #pragma unroll
                        for (int nt = 0; nt < 4; nt++)
                            mma_f16(acc[mh * 2 + m2][nt],
                                    A0[m2][2 * s], A8[m2][2 * s],
                                    A0[m2][2 * s + 1], A8[m2][2 * s + 1],
                                    B[nt][2 * s], B[nt][2 * s + 1]);
            }
        }
    }

    // epilogue: direct STG of fragments
    #pragma unroll
    for (int mt = 0; mt < 4; mt++) {
        #pragma unroll
        for (int nt = 0; nt < 4; nt++) {
            int m = bm0 + wm + mt * 16 + g;
            int n = bn0 + wn + nt * 8 + t4 * 2;
            *(float2*)&g_V[(size_t)m * 4096 + n]       = make_float2(acc[mt][nt][0], acc[mt][nt][1]);
            *(float2*)&g_V[(size_t)(m + 8) * 4096 + n] = make_float2(acc[mt][nt][2], acc[mt][nt][3]);
        }
    }
}

// ---- Kernel 2: LayerNorms + LSTM elementwise -------------------------------

__device__ __forceinline__ float sigm(float v) { return 1.f / (1.f + expf(-v)); }

__global__ __launch_bounds__(256)
void ln_lstm(const float* __restrict__ c,
             const float* __restrict__ b_ih,
             const float* __restrict__ gamma_ifgo, const float* __restrict__ beta_ifgo,
             const float* __restrict__ gamma_c,    const float* __restrict__ beta_c,
             float* __restrict__ out) {
    __shared__ float red[8][8];
    __shared__ float red2[8][2];

    const int b   = blockIdx.x;
    const int tid = threadIdx.x;
    const int w   = tid >> 5;

    const float4* vb   = (const float4*)(g_V + (size_t)b * 4096);
    const float4* bih4 = (const float4*)b_ih;

    float4 wv[4];
    float  s[4], ss[4];
    #pragma unroll
    for (int g = 0; g < 4; g++) {
        float4 t  = vb[g * 256 + tid];
        float4 bb = bih4[g * 256 + tid];
        t.x += bb.x; t.y += bb.y; t.z += bb.z; t.w += bb.w;
        wv[g] = t;
        s[g]  = t.x + t.y + t.z + t.w;
        ss[g] = t.x * t.x + t.y * t.y + t.z * t.z + t.w * t.w;
    }
    #pragma unroll
    for (int o = 16; o > 0; o >>= 1) {
        #pragma unroll
        for (int g = 0; g < 4; g++) {
            s[g]  += __shfl_xor_sync(0xffffffffu, s[g],  o);
            ss[g] += __shfl_xor_sync(0xffffffffu, ss[g], o);
        }
    }
    if ((tid & 31) == 0) {
        #pragma unroll
        for (int g = 0; g < 4; g++) { red[w][g * 2] = s[g]; red[w][g * 2 + 1] = ss[g]; }
    }
    __syncthreads();

    float4 gate[4];
    #pragma unroll
    for (int g = 0; g < 4; g++) {
        float S = 0.f, SS = 0.f;
        #pragma unroll
        for (int i = 0; i < 8; i++) { S += red[i][g * 2]; SS += red[i][g * 2 + 1]; }
        float mean = S * (1.f / 1024.f);
        float var  = fmaxf(SS - S * mean, 0.f) * (1.f / 1023.f);
        float inv  = 1.f / (sqrtf(var) + 1e-6f);
        float4 ga = ((const float4*)gamma_ifgo)[g * 256 + tid];
        float4 be = ((const float4*)beta_ifgo)[g * 256 + tid];
        gate[g].x = ga.x * (wv[g].x - mean) * inv + be.x;
        gate[g].y = ga.y * (wv[g].y - mean) * inv + be.y;
        gate[g].z = ga.z * (wv[g].z - mean) * inv + be.z;
        gate[g].w = ga.w * (wv[g].w - mean) * inv + be.w;
    }

    float4 ci = ((const float4*)(c + (size_t)b * 1024))[tid];
    float4 cc;
    cc.x = ci.x * sigm(gate[1].x + 1.f) + sigm(gate[0].x) * tanhf(gate[2].x);
    cc.y = ci.y * sigm(gate[1].y + 1.f) + sigm(gate[0].y) * tanhf(gate[2].y);
    cc.z = ci.z * sigm(gate[1].z + 1.f) + sigm(gate[0].z) * tanhf(gate[2].z);
    cc.w = ci.w * sigm(gate[1].w + 1.f) + sigm(gate[0].w) * tanhf(gate[2].w);

    float s2  = cc.x + cc.y + cc.z + cc.w;
    float ss2 = cc.x * cc.x + cc.y * cc.y + cc.z * cc.z + cc.w * cc.w;
    #pragma unroll
    for (int o = 16; o > 0; o >>= 1) {
        s2  += __shfl_xor_sync(0xffffffffu, s2,  o);
        ss2 += __shfl_xor_sync(0xffffffffu, ss2, o);
    }
    if ((tid & 31) == 0) { red2[w][0] = s2; red2[w][1] = ss2; }
    __syncthreads();
    float S = 0.f, SS = 0.f;
    #pragma unroll
    for (int i = 0; i < 8; i++) { S += red2[i][0]; SS += red2[i][1]; }
    float mean = S * (1.f / 1024.f);
    float var  = fmaxf(SS - S * mean, 0.f) * (1.f / 1023.f);
    float inv  = 1.f / (sqrtf(var) + 1e-6f);

    float4 gc = ((const float4*)gamma_c)[tid];
    float4 bc = ((const float4*)beta_c)[tid];
    float4 nc, nh;
    nc.x = gc.x * (cc.x - mean) * inv + bc.x;  nh.x = tanhf(nc.x) * sigm(gate[3].x);
    nc.y = gc.y * (cc.y - mean) * inv + bc.y;  nh.y = tanhf(nc.y) * sigm(gate[3].y);
    nc.z = gc.z * (cc.z - mean) * inv + bc.z;  nh.z = tanhf(nc.z) * sigm(gate[3].z);
    nc.w = gc.w * (cc.w - mean) * inv + bc.w;  nh.w = tanhf(nc.w) * sigm(gate[3].w);

    ((float4*)out)[(size_t)b * 256 + tid]                      = nh;
    ((float4*)out)[(size_t)4096 * 256 + (size_t)b * 256 + tid] = nc;
}

// ---- launch ----------------------------------------------------------------

extern "C" void kernel_launch(void* const* d_in, const int* in_sizes, int n_in,
                              void* d_out, int out_size) {
    const float* x     = (const float*)d_in[0];
    const float* h     = (const float*)d_in[1];
    const float* c     = (const float*)d_in[2];
    const float* Wih   = (const float*)d_in[3];
    const float* bih   = (const float*)d_in[4];
    const float* Whh   = (const float*)d_in[5];
    const float* gifgo = (const float*)d_in[6];
    const float* bifgo = (const float*)d_in[7];
    const float* gc    = (const float*)d_in[8];
    const float* bc    = (const float*)d_in[9];
    float* out = (float*)d_out;

    __half *gA, *gW;
    cudaGetSymbolAddress((void**)&gA, g_A);
    cudaGetSymbolAddress((void**)&gW, g_W);

    cudaFuncSetAttribute(gemm_f16, cudaFuncAttributeMaxDynamicSharedMemorySize, SMEM_SZ);

    tohalf<<<2048, 256>>>(x, h, Wih, Whh);
    dim3 grid(4096 / BN, 4096 / BM);            // 32 x 32
    gemm_f16<<<grid, 256, SMEM_SZ>>>(gA, gW);
    ln_lstm<<<4096, 256>>>(c, bih, gifgo, bifgo, gc, bc, out);
}

// round 11
// speedup vs baseline: 1.6712x; 1.0446x over previous
#include <cuda_runtime.h>
#include <cuda_fp16.h>
#include <cstdint>

// ---------------------------------------------------------------------------
// Fused LayerNorm-LSTM cell, sm_100 legacy tensor path.
//   Kernel 0: convert x,h -> g_A (fp16), Wih,Whh -> g_W (fp16), k-permuted so
//             m16n8k16 fragments are single lds.128 ops. 1 thread = 16B out.
//   Kernel 1: v = A @ W^T via mma.sync.m16n8k16.f16 -> g_V f32
//             128x128 tiles, 64x32 warp tiles, NS=3, 2 CTAs/SM (regfile-full).
//   Kernel 2: 4x LN + LSTM elementwise + LN -> out (fast ex2-based activations)
// ---------------------------------------------------------------------------

#define BM 128
#define BN 128
#define BKH 64                          // k halfs per stage (128 B per row)
#define NS 3
#define NT 32                           // 2048 / 64
#define A_BYTES (BM * 128)              // 16384
#define STAGE_BYTES ((BM + BN) * 128)   // 32768
#define SMEM_SZ (NS * STAGE_BYTES + 1024)   // 99328

__device__ float  g_V[4096u * 4096u];   // 64 MB pre-LN gate activations
__device__ __half g_A[4096u * 2048u];   // 16 MB fp16 [x|h], k-permuted
__device__ __half g_W[4096u * 2048u];   // 16 MB fp16 [Wih|Whh], k-permuted

// ---- helpers ---------------------------------------------------------------

__device__ __forceinline__ uint32_t s2u(const void* p) {
    return (uint32_t)__cvta_generic_to_shared(p);
}
__device__ __forceinline__ void cp_async16(uint32_t dst, const void* src) {
    asm volatile("cp.async.cg.shared.global [%0], [%1], 16;\n" :: "r"(dst), "l"(src));
}
__device__ __forceinline__ void cp_commit() {
    asm volatile("cp.async.commit_group;\n" ::: "memory");
}
template <int N> __device__ __forceinline__ void cp_wait() {
    asm volatile("cp.async.wait_group %0;\n" :: "n"(N) : "memory");
}
__device__ __forceinline__ void lds128(uint32_t* v, uint32_t a) {
    asm volatile("ld.shared.v4.b32 {%0,%1,%2,%3}, [%4];"
                 : "=r"(v[0]), "=r"(v[1]), "=r"(v[2]), "=r"(v[3]) : "r"(a));
}
__device__ __forceinline__ void mma_f16(float* d, uint32_t a0, uint32_t a1,
                                        uint32_t a2, uint32_t a3,
                                        uint32_t b0, uint32_t b1) {
    asm volatile(
        "mma.sync.aligned.m16n8k16.row.col.f32.f16.f16.f32 "
        "{%0,%1,%2,%3}, {%4,%5,%6,%7}, {%8,%9}, {%0,%1,%2,%3};\n"
        : "+f"(d[0]), "+f"(d[1]), "+f"(d[2]), "+f"(d[3])
        : "r"(a0), "r"(a1), "r"(a2), "r"(a3), "r"(b0), "r"(b1));
}

// ---- Kernel 0: fp16 convert + k-permute, 1 thread per 16B output -----------
// Output quarter i of a 32-half block holds source floats, in order:
// {2i, 2i+1, 2i+8, 2i+9, 2i+16, 2i+17, 2i+24, 2i+25}  (verified == the
// pos = ((k>>1)&3)*8 + ((k>>4)&1)*4 + ((k>>3)&1)*2 + (k&1) permutation).

__global__ __launch_bounds__(256)
void tohalf(const float* __restrict__ x, const float* __restrict__ h,
            const float* __restrict__ Wih, const float* __restrict__ Whh) {
    const uint32_t q = blockIdx.x * 256u + threadIdx.x;     // 0 .. 2M-1
    const uint32_t tensor = q >> 20;                        // 0=A, 1=W
    const uint32_t r = q & 0xFFFFFu;
    const uint32_t blk = r >> 2;                            // 32-half block id
    const uint32_t i = r & 3u;                              // quarter 0..3
    const uint32_t row = blk >> 6;
    const uint32_t chunk = blk & 63u;

    const float* src;
    __half* dst;
    if (tensor == 0) {
        src = (chunk < 32u) ? x + (size_t)row * 1024 + chunk * 32
                            : h + (size_t)row * 1024 + (chunk - 32u) * 32;
        dst = g_A + (size_t)row * 2048 + chunk * 32;
    } else {
        src = (chunk < 32u) ? Wih + (size_t)row * 1024 + chunk * 32
                            : Whh + (size_t)row * 1024 + (chunk - 32u) * 32;
        dst = g_W + (size_t)row * 2048 + chunk * 32;
    }

    const float2* p = (const float2*)src + i;
    float2 a = p[0], b = p[4], c2 = p[8], d = p[12];
    union { __half2 h2[4]; uint4 u; } o;
    o.h2[0] = __float22half2_rn(a);
    o.h2[1] = __float22half2_rn(b);
    o.h2[2] = __float22half2_rn(c2);
    o.h2[3] = __float22half2_rn(d);
    ((uint4*)dst)[i] = o.u;
}

// ---- Kernel 1: fp16 GEMM, 2 CTAs/SM (unchanged from R10 best) ---------------

__global__ __launch_bounds__(256, 2)
void gemm_f16(const __half* __restrict__ gA, const __half* __restrict__ gW) {
    extern __shared__ float dsm[];
    const uint32_t dyn0 = s2u(dsm);
    const uint32_t base = (dyn0 + 1023u) & ~1023u;

    const int tid  = threadIdx.x;
    const int warp = tid >> 5;
    const int lane = tid & 31;
    const int g    = lane >> 2;               // 0..7
    const int t4   = lane & 3;                // 0..3
    const int wm = (warp & 1) * 64;           // 2 x 4 warp grid, 64x32 warp tile
    const int wn = (warp >> 1) * 32;
    const int bm0 = blockIdx.y * BM;
    const int bn0 = blockIdx.x * BN;
    const uint32_t gpar = (uint32_t)(g & 1);

    float acc[4][4][4];
    #pragma unroll
    for (int i = 0; i < 4; i++)
        #pragma unroll
        for (int j = 0; j < 4; j++)
            #pragma unroll
            for (int k = 0; k < 4; k++) acc[i][j][k] = 0.f;

    const int lrow = tid >> 1;
    const int lc0  = (tid & 1) * 4;
    const uint32_t lsw = (uint32_t)(lrow & 1) << 2;

    auto issue_loads = [&](int kt) {
        const uint32_t sb = base + (uint32_t)(kt % NS) * STAGE_BYTES;
        const __half* arow = gA + (size_t)(bm0 + lrow) * 2048 + kt * BKH;
        const __half* brow = gW + (size_t)(bn0 + lrow) * 2048 + kt * BKH;
        #pragma unroll
        for (int j = 0; j < 4; j++) {
            int c = lc0 + j;
            uint32_t coff = ((uint32_t)c ^ lsw) * 16u;
            cp_async16(sb + (uint32_t)lrow * 128u + coff,           arow + c * 8);
            cp_async16(sb + A_BYTES + (uint32_t)lrow * 128u + coff, brow + c * 8);
        }
        cp_commit();
    };

    issue_loads(0); issue_loads(1);

    for (int kt = 0; kt < NT; kt++) {
        if (kt < NT - 1) cp_wait<1>();
        else             cp_wait<0>();
        __syncthreads();

        if (kt + NS - 1 < NT) issue_loads(kt + NS - 1);

        const uint32_t sA = base + (uint32_t)(kt % NS) * STAGE_BYTES;
        const uint32_t sB = sA + A_BYTES;
        const uint32_t tof = (uint32_t)t4 * 16u;

        #pragma unroll
        for (int i = 0; i < 2; i++) {                     // 32-half sub-blocks
            const uint32_t ie = ((uint32_t)i ^ gpar) * 64u;

            uint32_t B[4][4];
            #pragma unroll
            for (int nt = 0; nt < 4; nt++)
                lds128(B[nt], sB + (uint32_t)(wn + nt * 8 + g) * 128u + ie + tof);

            #pragma unroll
            for (int mh = 0; mh < 2; mh++) {
                uint32_t A0[2][4], A8[2][4];
                #pragma unroll
                for (int m2 = 0; m2 < 2; m2++) {
                    uint32_t ad = sA + (uint32_t)(wm + (mh * 2 + m2) * 16 + g) * 128u + ie + tof;
                    lds128(A0[m2], ad);
                    lds128(A8[m2], ad + 8 * 128);
                }
                #pragma unroll
                for (int s = 0; s < 2; s++)
                    #pragma unroll
                    for (int m2 = 0; m2 < 2; m2++)
                        #pragma unroll
                        for (int nt = 0; nt < 4; nt++)
                            mma_f16(acc[mh * 2 + m2][nt],
                                    A0[m2][2 * s], A8[m2][2 * s],
                                    A0[m2][2 * s + 1], A8[m2][2 * s + 1],
                                    B[nt][2 * s], B[nt][2 * s + 1]);
            }
        }
    }

    #pragma unroll
    for (int mt = 0; mt < 4; mt++) {
        #pragma unroll
        for (int nt = 0; nt < 4; nt++) {
            int m = bm0 + wm + mt * 16 + g;
            int n = bn0 + wn + nt * 8 + t4 * 2;
            *(float2*)&g_V[(size_t)m * 4096 + n]       = make_float2(acc[mt][nt][0], acc[mt][nt][1]);
            *(float2*)&g_V[(size_t)(m + 8) * 4096 + n] = make_float2(acc[mt][nt][2], acc[mt][nt][3]);
        }
    }
}

// ---- Kernel 2: LayerNorms + LSTM elementwise (fast activations) -------------

__device__ __forceinline__ float sigm(float v) {
    return __fdividef(1.f, 1.f + __expf(-v));
}
__device__ __forceinline__ float tanh_f(float v) {
    return fmaf(2.f, sigm(2.f * v), -1.f);      // tanh(x) = 2*sig(2x) - 1
}

__global__ __launch_bounds__(256)
void ln_lstm(const float* __restrict__ c,
             const float* __restrict__ b_ih,
             const float* __restrict__ gamma_ifgo, const float* __restrict__ beta_ifgo,
             const float* __restrict__ gamma_c,    const float* __restrict__ beta_c,
             float* __restrict__ out) {
    __shared__ float red[8][8];
    __shared__ float red2[8][2];

    const int b   = blockIdx.x;
    const int tid = threadIdx.x;
    const int w   = tid >> 5;

    const float4* vb   = (const float4*)(g_V + (size_t)b * 4096);
    const float4* bih4 = (const float4*)b_ih;

    float4 wv[4];
    float  s[4], ss[4];
    #pragma unroll
    for (int g = 0; g < 4; g++) {
        float4 t  = vb[g * 256 + tid];
        float4 bb = bih4[g * 256 + tid];
        t.x += bb.x; t.y += bb.y; t.z += bb.z; t.w += bb.w;
        wv[g] = t;
        s[g]  = t.x + t.y + t.z + t.w;
        ss[g] = t.x * t.x + t.y * t.y + t.z * t.z + t.w * t.w;
    }
    #pragma unroll
    for (int o = 16; o > 0; o >>= 1) {
        #pragma unroll
        for (int g = 0; g < 4; g++) {
            s[g]  += __shfl_xor_sync(0xffffffffu, s[g],  o);
            ss[g] += __shfl_xor_sync(0xffffffffu, ss[g], o);
        }
    }
    if ((tid & 31) == 0) {
        #pragma unroll
        for (int g = 0; g < 4; g++) { red[w][g * 2] = s[g]; red[w][g * 2 + 1] = ss[g]; }
    }
    __syncthreads();

    float4 gate[4];
    #pragma unroll
    for (int g = 0; g < 4; g++) {
        float S = 0.f, SS = 0.f;
        #pragma unroll
        for (int i = 0; i < 8; i++) { S += red[i][g * 2]; SS += red[i][g * 2 + 1]; }
        float mean = S * (1.f / 1024.f);
        float var  = fmaxf(SS - S * mean, 0.f) * (1.f / 1023.f);
        float inv  = 1.f / (sqrtf(var) + 1e-6f);
        float4 ga = ((const float4*)gamma_ifgo)[g * 256 + tid];
        float4 be = ((const float4*)beta_ifgo)[g * 256 + tid];
        gate[g].x = ga.x * (wv[g].x - mean) * inv + be.x;
        gate[g].y = ga.y * (wv[g].y - mean) * inv + be.y;
        gate[g].z = ga.z * (wv[g].z - mean) * inv + be.z;
        gate[g].w = ga.w * (wv[g].w - mean) * inv + be.w;
    }

    float4 ci = ((const float4*)(c + (size_t)b * 1024))[tid];
    float4 cc;
    cc.x = ci.x * sigm(gate[1].x + 1.f) + sigm(gate[0].x) * tanh_f(gate[2].x);
    cc.y = ci.y * sigm(gate[1].y + 1.f) + sigm(gate[0].y) * tanh_f(gate[2].y);
    cc.z = ci.z * sigm(gate[1].z + 1.f) + sigm(gate[0].z) * tanh_f(gate[2].z);
    cc.w = ci.w * sigm(gate[1].w + 1.f) + sigm(gate[0].w) * tanh_f(gate[2].w);

    float s2  = cc.x + cc.y + cc.z + cc.w;
    float ss2 = cc.x * cc.x + cc.y * cc.y + cc.z * cc.z + cc.w * cc.w;
    #pragma unroll
    for (int o = 16; o > 0; o >>= 1) {
        s2  += __shfl_xor_sync(0xffffffffu, s2,  o);
        ss2 += __shfl_xor_sync(0xffffffffu, ss2, o);
    }
    if ((tid & 31) == 0) { red2[w][0] = s2; red2[w][1] = ss2; }
    __syncthreads();
    float S = 0.f, SS = 0.f;
    #pragma unroll
    for (int i = 0; i < 8; i++) { S += red2[i][0]; SS += red2[i][1]; }
    float mean = S * (1.f / 1024.f);
    float var  = fmaxf(SS - S * mean, 0.f) * (1.f / 1023.f);
    float inv  = 1.f / (sqrtf(var) + 1e-6f);

    float4 gc = ((const float4*)gamma_c)[tid];
    float4 bc = ((const float4*)beta_c)[tid];
    float4 nc, nh;
    nc.x = gc.x * (cc.x - mean) * inv + bc.x;  nh.x = tanh_f(nc.x) * sigm(gate[3].x);
    nc.y = gc.y * (cc.y - mean) * inv + bc.y;  nh.y = tanh_f(nc.y) * sigm(gate[3].y);
    nc.z = gc.z * (cc.z - mean) * inv + bc.z;  nh.z = tanh_f(nc.z) * sigm(gate[3].z);
    nc.w = gc.w * (cc.w - mean) * inv + bc.w;  nh.w = tanh_f(nc.w) * sigm(gate[3].w);

    ((float4*)out)[(size_t)b * 256 + tid]                      = nh;
    ((float4*)out)[(size_t)4096 * 256 + (size_t)b * 256 + tid] = nc;
}

// ---- launch ----------------------------------------------------------------

extern "C" void kernel_launch(void* const* d_in, const int* in_sizes, int n_in,
                              void* d_out, int out_size) {
    const float* x     = (const float*)d_in[0];
    const float* h     = (const float*)d_in[1];
    const float* c     = (const float*)d_in[2];
    const float* Wih   = (const float*)d_in[3];
    const float* bih   = (const float*)d_in[4];
    const float* Whh   = (const float*)d_in[5];
    const float* gifgo = (const float*)d_in[6];
    const float* bifgo = (const float*)d_in[7];
    const float* gc    = (const float*)d_in[8];
    const float* bc    = (const float*)d_in[9];
    float* out = (float*)d_out;

    __half *gA, *gW;
    cudaGetSymbolAddress((void**)&gA, g_A);
    cudaGetSymbolAddress((void**)&gW, g_W);

    cudaFuncSetAttribute(gemm_f16, cudaFuncAttributeMaxDynamicSharedMemorySize, SMEM_SZ);

    tohalf<<<8192, 256>>>(x, h, Wih, Whh);
    dim3 grid(4096 / BN, 4096 / BM);            // 32 x 32
    gemm_f16<<<grid, 256, SMEM_SZ>>>(gA, gW);
    ln_lstm<<<4096, 256>>>(c, bih, gifgo, bifgo, gc, bc, out);
}